// round 3
// baseline (speedup 1.0000x reference)
#include <cuda_runtime.h>
#include <math.h>

#define Bz 2
#define TX 1024
#define TY 4096
#define CC 768
#define HH 12
#define DD 64

// Scratch (allocation-free rule: __device__ globals)
__device__ float g_q[(size_t)Bz * HH * TX * DD];   // 6 MB
__device__ float g_k[(size_t)Bz * HH * TY * DD];   // 24 MB
__device__ float g_v[(size_t)Bz * HH * TY * DD];   // 24 MB
__device__ float g_o[(size_t)Bz * TX * CC];        // 6 MB

// ---------------------------------------------------------------------------
// Tiled fp32 GEMM: C[M,N] = A[M,K] @ W[K,N], 64x64 tile, 4x4 microtile.
// MODE 0: A=x, fused RoPE epilogue -> g_q[B,H,TX,D]
// MODE 1: A=y, epilogue splits K (RoPE) -> g_k and V -> g_v
// MODE 2: A=g_o, plain epilogue -> Out
// ---------------------------------------------------------------------------
template <int MODE>
__global__ void __launch_bounds__(256)
gemm_kernel(const float* __restrict__ A, const float* __restrict__ W,
            float* __restrict__ Out, int M, int N, int K,
            const float* __restrict__ tvec, const float* __restrict__ invf)
{
    __shared__ __align__(16) float As[16][65];   // [k][m], padded
    __shared__ __align__(16) float Bs[16][68];   // [k][n], padded (16B-friendly)

    const int tid = threadIdx.x;
    const int ty = tid >> 4, tx = tid & 15;
    const int m0 = blockIdx.y * 64, n0 = blockIdx.x * 64;
    const int a_r = tid >> 2, a_k = (tid & 3) * 4;
    const int b_r = tid >> 4, b_c = (tid & 15) * 4;

    const float* Ap = (MODE == 2) ? (const float*)g_o : A;

    float acc[4][4];
#pragma unroll
    for (int i = 0; i < 4; i++)
#pragma unroll
        for (int j = 0; j < 4; j++) acc[i][j] = 0.f;

    for (int kk = 0; kk < K; kk += 16) {
        float4 av = *(const float4*)&Ap[(size_t)(m0 + a_r) * K + kk + a_k];
        As[a_k + 0][a_r] = av.x;
        As[a_k + 1][a_r] = av.y;
        As[a_k + 2][a_r] = av.z;
        As[a_k + 3][a_r] = av.w;
        float4 bv = *(const float4*)&W[(size_t)(kk + b_r) * N + n0 + b_c];
        *(float4*)&Bs[b_r][b_c] = bv;
        __syncthreads();
#pragma unroll
        for (int k = 0; k < 16; k++) {
            float4 b4 = *(const float4*)&Bs[k][tx * 4];
            float a4[4];
#pragma unroll
            for (int i = 0; i < 4; i++) a4[i] = As[k][ty * 4 + i];
            const float bb[4] = {b4.x, b4.y, b4.z, b4.w};
#pragma unroll
            for (int i = 0; i < 4; i++)
#pragma unroll
                for (int j = 0; j < 4; j++) acc[i][j] = fmaf(a4[i], bb[j], acc[i][j]);
        }
        __syncthreads();
    }

#pragma unroll
    for (int i = 0; i < 4; i++) {
        int m = m0 + ty * 4 + i;
        if (MODE == 0) {
            float pos = tvec[m];
            int b = m / TX, t = m % TX;
#pragma unroll
            for (int p = 0; p < 2; p++) {
                int n = n0 + tx * 4 + 2 * p;
                int h = n / DD, d = n % DD;
                float f = pos * invf[d >> 1];
                float sn, cs;
                sincosf(f, &sn, &cs);
                float a0 = acc[i][2 * p], a1 = acc[i][2 * p + 1];
                size_t base = ((size_t)(b * HH + h) * TX + t) * DD + d;
                g_q[base]     = a0 * cs - a1 * sn;
                g_q[base + 1] = a1 * cs + a0 * sn;
            }
        } else if (MODE == 1) {
            float pos = tvec[m];
            int b = m / TY, t = m % TY;
#pragma unroll
            for (int p = 0; p < 2; p++) {
                int n = n0 + tx * 4 + 2 * p;
                if (n < CC) {  // K path with RoPE (uniform per block: n0 tiles of 64)
                    int h = n / DD, d = n % DD;
                    float f = pos * invf[d >> 1];
                    float sn, cs;
                    sincosf(f, &sn, &cs);
                    float a0 = acc[i][2 * p], a1 = acc[i][2 * p + 1];
                    size_t base = ((size_t)(b * HH + h) * TY + t) * DD + d;
                    g_k[base]     = a0 * cs - a1 * sn;
                    g_k[base + 1] = a1 * cs + a0 * sn;
                } else {       // V path, no RoPE
                    int nv = n - CC;
                    int h = nv / DD, d = nv % DD;
                    size_t base = ((size_t)(b * HH + h) * TY + t) * DD + d;
                    g_v[base]     = acc[i][2 * p];
                    g_v[base + 1] = acc[i][2 * p + 1];
                }
            }
        } else {
#pragma unroll
            for (int j = 0; j < 4; j++)
                Out[(size_t)m * N + n0 + tx * 4 + j] = acc[i][j];
        }
    }
}

// ---------------------------------------------------------------------------
// Windowed flash attention. Grid (TX/64, H, B), 256 threads.
// Key range per 64-query tile found by binary search on sorted y_t
// (valid keys are contiguous: yt in [xt - dist, xt]).
// ---------------------------------------------------------------------------
__global__ void __launch_bounds__(256)
flash_kernel(const float* __restrict__ xt, const float* __restrict__ yt,
             const int* __restrict__ p_dist, const int* __restrict__ p_mind)
{
    extern __shared__ float sm[];
    float* q_s  = sm;             // 64*65
    float* k_s  = sm + 4160;      // 64*65
    float* v_s  = sm + 8320;      // 64*65
    float* s_s  = sm + 12480;     // 64*65
    float* xt_s = sm + 16640;     // 64
    float* kt_s = xt_s + 64;      // 64
    float* m_s  = kt_s + 64;      // 64
    float* l_s  = m_s + 64;       // 64
    float* f_s  = l_s + 64;       // 64
    __shared__ int rng[2];

    const int tid = threadIdx.x;
    const int ty = tid >> 4, tx = tid & 15;
    const int q0 = blockIdx.x * 64;
    const int h  = blockIdx.y;
    const int b  = blockIdx.z;
    const float distf = (float)p_dist[0];
    const float mindf = (float)p_mind[0];

    const float* Qg = g_q + ((size_t)(b * HH + h) * TX + q0) * DD;
    const float* Kg = g_k + (size_t)(b * HH + h) * TY * DD;
    const float* Vg = g_v + (size_t)(b * HH + h) * TY * DD;
    const float* Y  = yt + (size_t)b * TY;

    for (int idx = tid; idx < 64 * 64; idx += 256) {
        int r = idx >> 6, d = idx & 63;
        q_s[r * 65 + d] = Qg[r * DD + d];
    }
    if (tid < 64) {
        xt_s[tid] = xt[(size_t)b * TX + q0 + tid] - mindf;
        m_s[tid] = -1e30f;
        l_s[tid] = 0.f;
    }
    if (tid == 0) {
        float xmin = xt[(size_t)b * TX + q0] - mindf;
        float xmax = xt[(size_t)b * TX + q0 + 63] - mindf;
        int lo = 0, hi = TY;
        while (lo < hi) { int mid = (lo + hi) >> 1; if (Y[mid] >= xmin - distf) hi = mid; else lo = mid + 1; }
        rng[0] = lo & ~63;
        lo = 0; hi = TY;
        while (lo < hi) { int mid = (lo + hi) >> 1; if (Y[mid] > xmax) hi = mid; else lo = mid + 1; }
        rng[1] = lo;
    }
    __syncthreads();
    const int ks = rng[0], ke = rng[1];

    float o[4][4];
#pragma unroll
    for (int i = 0; i < 4; i++)
#pragma unroll
        for (int j = 0; j < 4; j++) o[i][j] = 0.f;

    for (int kb = ks; kb < ke; kb += 64) {
        for (int idx = tid; idx < 64 * 64; idx += 256) {
            int c = idx >> 6, d = idx & 63;
            int gi = kb + c;
            float kv = 0.f, vv = 0.f;
            if (gi < TY) { kv = Kg[(size_t)gi * DD + d]; vv = Vg[(size_t)gi * DD + d]; }
            k_s[c * 65 + d] = kv;
            v_s[c * 65 + d] = vv;
        }
        if (tid < 64) kt_s[tid] = (kb + tid < TY) ? Y[kb + tid] : 3e38f;
        __syncthreads();

        // S = Q K^T (4x4 microtile per thread)
        float acc[4][4];
#pragma unroll
        for (int i = 0; i < 4; i++)
#pragma unroll
            for (int j = 0; j < 4; j++) acc[i][j] = 0.f;
#pragma unroll 16
        for (int d = 0; d < 64; d++) {
            float a4[4], b4[4];
#pragma unroll
            for (int i = 0; i < 4; i++) a4[i] = q_s[(ty * 4 + i) * 65 + d];
#pragma unroll
            for (int j = 0; j < 4; j++) b4[j] = k_s[(tx * 4 + j) * 65 + d];
#pragma unroll
            for (int i = 0; i < 4; i++)
#pragma unroll
                for (int j = 0; j < 4; j++) acc[i][j] = fmaf(a4[i], b4[j], acc[i][j]);
        }
        // scale + mask + store to smem
#pragma unroll
        for (int i = 0; i < 4; i++) {
            int r = ty * 4 + i;
            float xv = xt_s[r];
#pragma unroll
            for (int j = 0; j < 4; j++) {
                int c = tx * 4 + j;
                float yv = kt_s[c];
                bool ok = (xv >= yv) && (xv <= yv + distf);
                s_s[r * 65 + c] = ok ? acc[i][j] * 0.125f : -1e30f;
            }
        }
        __syncthreads();

        // online softmax: 4 threads per row, 16 cols each
        {
            int row = tid >> 2, jj = tid & 3;
            int c0 = jj * 16;
            float mx = -1e30f;
#pragma unroll
            for (int c = 0; c < 16; c++) mx = fmaxf(mx, s_s[row * 65 + c0 + c]);
            mx = fmaxf(mx, __shfl_xor_sync(0xffffffffu, mx, 1));
            mx = fmaxf(mx, __shfl_xor_sync(0xffffffffu, mx, 2));
            float m_old = m_s[row];
            float m_new = fmaxf(m_old, mx);
            float sum = 0.f;
#pragma unroll
            for (int c = 0; c < 16; c++) {
                float sv = s_s[row * 65 + c0 + c];
                float pv = (sv <= -1e29f) ? 0.f : __expf(sv - m_new);
                s_s[row * 65 + c0 + c] = pv;
                sum += pv;
            }
            sum += __shfl_xor_sync(0xffffffffu, sum, 1);
            sum += __shfl_xor_sync(0xffffffffu, sum, 2);
            if (jj == 0) {
                float fct = __expf(m_old - m_new);
                l_s[row] = l_s[row] * fct + sum;
                m_s[row] = m_new;
                f_s[row] = fct;
            }
        }
        __syncthreads();

        // O = O*corr + P @ V
        float fct[4];
#pragma unroll
        for (int i = 0; i < 4; i++) fct[i] = f_s[ty * 4 + i];
#pragma unroll
        for (int i = 0; i < 4; i++)
#pragma unroll
            for (int j = 0; j < 4; j++) o[i][j] *= fct[i];
#pragma unroll 16
        for (int c = 0; c < 64; c++) {
            float p4[4], v4[4];
#pragma unroll
            for (int i = 0; i < 4; i++) p4[i] = s_s[(ty * 4 + i) * 65 + c];
#pragma unroll
            for (int j = 0; j < 4; j++) v4[j] = v_s[c * 65 + tx * 4 + j];
#pragma unroll
            for (int i = 0; i < 4; i++)
#pragma unroll
                for (int j = 0; j < 4; j++) o[i][j] = fmaf(p4[i], v4[j], o[i][j]);
        }
        __syncthreads();
    }

    // epilogue: divide by l, write o in [B,TX,C] layout
#pragma unroll
    for (int i = 0; i < 4; i++) {
        int r = ty * 4 + i;
        float l = l_s[r];
        float rcp = (l > 0.f) ? 1.f / l : 0.f;
#pragma unroll
        for (int j = 0; j < 4; j++)
            g_o[((size_t)b * TX + q0 + r) * CC + h * DD + tx * 4 + j] = o[i][j] * rcp;
    }
}

extern "C" void kernel_launch(void* const* d_in, const int* in_sizes, int n_in,
                              void* d_out, int out_size) {
    const float* x    = (const float*)d_in[0];
    const float* x_t  = (const float*)d_in[1];
    const float* y    = (const float*)d_in[2];
    const float* y_t  = (const float*)d_in[3];
    const int*   dist = (const int*)d_in[4];
    const int*   mind = (const int*)d_in[5];
    const float* Wq   = (const float*)d_in[6];
    const float* Wkv  = (const float*)d_in[7];
    const float* Wpr  = (const float*)d_in[8];
    const float* invf = (const float*)d_in[9];
    float* out = (float*)d_out;

    // q = rope(x @ Wq)
    gemm_kernel<0><<<dim3(CC / 64, (Bz * TX) / 64), 256>>>(
        x, Wq, nullptr, Bz * TX, CC, CC, x_t, invf);
    // kv = y @ Wkv ; k = rope(kv[:, :C]) ; v = kv[:, C:]
    gemm_kernel<1><<<dim3((2 * CC) / 64, (Bz * TY) / 64), 256>>>(
        y, Wkv, nullptr, Bz * TY, 2 * CC, CC, y_t, invf);
    // windowed flash attention
    const int smem_bytes = 16960 * 4;  // 67840
    cudaFuncSetAttribute(flash_kernel, cudaFuncAttributeMaxDynamicSharedMemorySize, smem_bytes);
    flash_kernel<<<dim3(TX / 64, HH, Bz), 256, smem_bytes>>>(x_t, y_t, dist, mind);
    // out = o @ Wproj
    gemm_kernel<2><<<dim3(CC / 64, (Bz * TX) / 64), 256>>>(
        nullptr, Wpr, out, Bz * TX, CC, CC, nullptr, nullptr);
}

// round 6
// speedup vs baseline: 1.8283x; 1.8283x over previous
#include <cuda_runtime.h>
#include <cuda_bf16.h>
#include <math.h>
#include <stdint.h>

#define Bz 2
#define TX 1024
#define TY 4096
#define CC 768
#define HH 12
#define DD 64

// Scratch (allocation-free rule: __device__ globals)
__device__ float g_q[(size_t)Bz * HH * TX * DD];
__device__ float g_k[(size_t)Bz * HH * TY * DD];
__device__ float g_v[(size_t)Bz * HH * TY * DD];
__device__ float g_o[(size_t)Bz * TX * CC];

// bf16 hi/lo splits of activations ([M][K] row-major)
__device__ __nv_bfloat16 gx_hi[(size_t)Bz * TX * CC];
__device__ __nv_bfloat16 gx_lo[(size_t)Bz * TX * CC];
__device__ __nv_bfloat16 gy_hi[(size_t)Bz * TY * CC];
__device__ __nv_bfloat16 gy_lo[(size_t)Bz * TY * CC];
__device__ __nv_bfloat16 go_hi[(size_t)Bz * TX * CC];
__device__ __nv_bfloat16 go_lo[(size_t)Bz * TX * CC];
// transposed weights [N][K] bf16 hi/lo
__device__ __nv_bfloat16 gwq_hi[(size_t)CC * CC];
__device__ __nv_bfloat16 gwq_lo[(size_t)CC * CC];
__device__ __nv_bfloat16 gwkv_hi[(size_t)2 * CC * CC];
__device__ __nv_bfloat16 gwkv_lo[(size_t)2 * CC * CC];
__device__ __nv_bfloat16 gwp_hi[(size_t)CC * CC];
__device__ __nv_bfloat16 gwp_lo[(size_t)CC * CC];

__device__ __forceinline__ void split_bf16(float x, __nv_bfloat16& h, __nv_bfloat16& l) {
    h = __float2bfloat16(x);
    l = __float2bfloat16(x - __bfloat162float(h));
}

// ---------------------------------------------------------------------------
// Prep: elementwise fp32 -> bf16 hi/lo split (same layout)
// ---------------------------------------------------------------------------
__global__ void __launch_bounds__(256)
fsplit(const float* __restrict__ A, __nv_bfloat16* __restrict__ hi,
       __nv_bfloat16* __restrict__ lo, int n4)
{
    int i = blockIdx.x * 256 + threadIdx.x;
    if (i >= n4) return;
    float4 v = ((const float4*)A)[i];
    __nv_bfloat16 h[4], l[4];
    split_bf16(v.x, h[0], l[0]); split_bf16(v.y, h[1], l[1]);
    split_bf16(v.z, h[2], l[2]); split_bf16(v.w, h[3], l[3]);
    ((uint2*)hi)[i] = *(uint2*)h;
    ((uint2*)lo)[i] = *(uint2*)l;
}

// ---------------------------------------------------------------------------
// Prep: W[K][N] fp32 -> Wt_hi/lo [N][K] bf16  (32x32 smem transpose)
// ---------------------------------------------------------------------------
__global__ void __launch_bounds__(256)
wtrans(const float* __restrict__ W, __nv_bfloat16* __restrict__ Thi,
       __nv_bfloat16* __restrict__ Tlo, int K, int N)
{
    __shared__ float sm[32][33];
    int n0 = blockIdx.x * 32, k0 = blockIdx.y * 32;
    int tx = threadIdx.x & 31, ty = threadIdx.x >> 5;
#pragma unroll
    for (int i = 0; i < 4; i++)
        sm[ty + 8 * i][tx] = W[(size_t)(k0 + ty + 8 * i) * N + n0 + tx];
    __syncthreads();
#pragma unroll
    for (int i = 0; i < 4; i++) {
        float v = sm[tx][ty + 8 * i];
        __nv_bfloat16 h, l;
        split_bf16(v, h, l);
        size_t o = (size_t)(n0 + ty + 8 * i) * K + k0 + tx;
        Thi[o] = h;
        Tlo[o] = l;
    }
}

// ---------------------------------------------------------------------------
// HMMA GEMM: C[M,N] = A[M,K] @ W[K,N] via bf16x3 split, mma.sync m16n8k16.
// CTA tile 128x128, 8 warps of 64x32, K-chunk 64 (one SW128 row).
// MODE 0: RoPE epilogue -> g_q   MODE 1: K(RoPE)->g_k, V->g_v   MODE 2: -> Out
// ---------------------------------------------------------------------------
#define SA_HI 0u
#define SA_LO 16384u
#define SB_HI 32768u
#define SB_LO 49152u
#define GEMM_SMEM 65536u

__device__ __forceinline__ void mma16816(float* c, const uint32_t* a, const uint32_t* b) {
    asm volatile(
        "mma.sync.aligned.m16n8k16.row.col.f32.bf16.bf16.f32 "
        "{%0,%1,%2,%3},{%4,%5,%6,%7},{%8,%9},{%0,%1,%2,%3};"
        : "+f"(c[0]), "+f"(c[1]), "+f"(c[2]), "+f"(c[3])
        : "r"(a[0]), "r"(a[1]), "r"(a[2]), "r"(a[3]), "r"(b[0]), "r"(b[1]));
}

template <int MODE>
__global__ void __launch_bounds__(256, 2)
gemm_mma(const __nv_bfloat16* __restrict__ Ahi, const __nv_bfloat16* __restrict__ Alo,
         const __nv_bfloat16* __restrict__ Bhi, const __nv_bfloat16* __restrict__ Blo,
         float* __restrict__ Out, int M, int N, int K,
         const float* __restrict__ tvec, const float* __restrict__ invf)
{
    extern __shared__ __align__(16) uint8_t smem[];
    const int tid = threadIdx.x;
    const int wid = tid >> 5, lane = tid & 31;
    const int wm = wid & 1, wn = wid >> 1;          // 2 x 4 warp grid
    const int m0 = blockIdx.y * 128, n0 = blockIdx.x * 128;
    const int lr = lane >> 2, lc = lane & 3;

    float acc[4][4][4];
#pragma unroll
    for (int a = 0; a < 4; a++)
#pragma unroll
        for (int b = 0; b < 4; b++)
#pragma unroll
            for (int c = 0; c < 4; c++) acc[a][b][c] = 0.f;

    const int NCH = K / 64;
    for (int ch = 0; ch < NCH; ch++) {
        const int k0 = ch * 64;
        // fill: each row is 64 bf16 = 128B = 8 uint4, SW128-swizzled granules
#pragma unroll
        for (int it = 0; it < 4; it++) {
            int i = tid + it * 256;          // 0..1023
            int r = i >> 3, t = i & 7;
            uint32_t soff = (uint32_t)(r * 128 + ((t ^ (r & 7)) << 4));
            size_t ga = (size_t)(m0 + r) * K + k0 + t * 8;
            *(uint4*)(smem + SA_HI + soff) = *(const uint4*)(Ahi + ga);
            *(uint4*)(smem + SA_LO + soff) = *(const uint4*)(Alo + ga);
            size_t gb = (size_t)(n0 + r) * K + k0 + t * 8;
            *(uint4*)(smem + SB_HI + soff) = *(const uint4*)(Bhi + gb);
            *(uint4*)(smem + SB_LO + soff) = *(const uint4*)(Blo + gb);
        }
        __syncthreads();

#pragma unroll
        for (int s = 0; s < 4; s++) {
            // B fragments: 4 n-tiles x {hi,lo} x 2 regs
            uint32_t bh[4][2], bl[4][2];
#pragma unroll
            for (int nt = 0; nt < 4; nt++) {
                int n = wn * 32 + nt * 8 + lr;
                uint32_t base = (uint32_t)(n * 128) + 4u * lc;
                uint32_t g0 = (uint32_t)(((2 * s) ^ (n & 7)) << 4);
                uint32_t g1 = (uint32_t)(((2 * s + 1) ^ (n & 7)) << 4);
                bh[nt][0] = *(uint32_t*)(smem + SB_HI + base + g0);
                bh[nt][1] = *(uint32_t*)(smem + SB_HI + base + g1);
                bl[nt][0] = *(uint32_t*)(smem + SB_LO + base + g0);
                bl[nt][1] = *(uint32_t*)(smem + SB_LO + base + g1);
            }
#pragma unroll
            for (int mt = 0; mt < 4; mt++) {
                int m1 = wm * 64 + mt * 16 + lr;
                int m2 = m1 + 8;
                uint32_t b1 = (uint32_t)(m1 * 128) + 4u * lc;
                uint32_t b2 = (uint32_t)(m2 * 128) + 4u * lc;
                uint32_t g10 = (uint32_t)(((2 * s) ^ (m1 & 7)) << 4);
                uint32_t g11 = (uint32_t)(((2 * s + 1) ^ (m1 & 7)) << 4);
                uint32_t g20 = (uint32_t)(((2 * s) ^ (m2 & 7)) << 4);
                uint32_t g21 = (uint32_t)(((2 * s + 1) ^ (m2 & 7)) << 4);
                uint32_t ah[4], al[4];
                ah[0] = *(uint32_t*)(smem + SA_HI + b1 + g10);
                ah[1] = *(uint32_t*)(smem + SA_HI + b2 + g20);
                ah[2] = *(uint32_t*)(smem + SA_HI + b1 + g11);
                ah[3] = *(uint32_t*)(smem + SA_HI + b2 + g21);
                al[0] = *(uint32_t*)(smem + SA_LO + b1 + g10);
                al[1] = *(uint32_t*)(smem + SA_LO + b2 + g20);
                al[2] = *(uint32_t*)(smem + SA_LO + b1 + g11);
                al[3] = *(uint32_t*)(smem + SA_LO + b2 + g21);
#pragma unroll
                for (int nt = 0; nt < 4; nt++) {
                    mma16816(acc[mt][nt], ah, bh[nt]);
                    mma16816(acc[mt][nt], ah, bl[nt]);
                    mma16816(acc[mt][nt], al, bh[nt]);
                }
            }
        }
        __syncthreads();
    }

    // ---- epilogue: fragments map cols (lc*2, lc*2+1) = RoPE pairs directly ----
#pragma unroll
    for (int mt = 0; mt < 4; mt++) {
        int mA = m0 + wm * 64 + mt * 16 + lr;
        int mB = mA + 8;
#pragma unroll
        for (int half = 0; half < 2; half++) {
            int m = half ? mB : mA;
            float pos = 0.f;
            int bb = 0, tt = 0;
            if (MODE == 0) { bb = m / TX; tt = m % TX; pos = tvec[m]; }
            if (MODE == 1) { bb = m / TY; tt = m % TY; pos = tvec[m]; }
#pragma unroll
            for (int nt = 0; nt < 4; nt++) {
                float c0 = acc[mt][nt][half * 2 + 0];
                float c1 = acc[mt][nt][half * 2 + 1];
                int col = n0 + wn * 32 + nt * 8 + 2 * lc;
                if (MODE == 2) {
                    float2 v = make_float2(c0, c1);
                    *(float2*)&Out[(size_t)m * N + col] = v;
                } else if (MODE == 0) {
                    int h = col / DD, dd = col % DD;
                    float f = pos * invf[dd >> 1];
                    float sn, cs;
                    sincosf(f, &sn, &cs);
                    float2 v = make_float2(c0 * cs - c1 * sn, c1 * cs + c0 * sn);
                    *(float2*)&g_q[((size_t)(bb * HH + h) * TX + tt) * DD + dd] = v;
                } else {
                    if (col < CC) {
                        int h = col / DD, dd = col % DD;
                        float f = pos * invf[dd >> 1];
                        float sn, cs;
                        sincosf(f, &sn, &cs);
                        float2 v = make_float2(c0 * cs - c1 * sn, c1 * cs + c0 * sn);
                        *(float2*)&g_k[((size_t)(bb * HH + h) * TY + tt) * DD + dd] = v;
                    } else {
                        int nv = col - CC;
                        int h = nv / DD, dd = nv % DD;
                        float2 v = make_float2(c0, c1);
                        *(float2*)&g_v[((size_t)(bb * HH + h) * TY + tt) * DD + dd] = v;
                    }
                }
            }
        }
    }
}

// ---------------------------------------------------------------------------
// Windowed flash attention (unchanged). Grid (TX/64, H, B), 256 threads.
// ---------------------------------------------------------------------------
__global__ void __launch_bounds__(256)
flash_kernel(const float* __restrict__ xt, const float* __restrict__ yt,
             const int* __restrict__ p_dist, const int* __restrict__ p_mind)
{
    extern __shared__ float sm[];
    float* q_s  = sm;
    float* k_s  = sm + 4160;
    float* v_s  = sm + 8320;
    float* s_s  = sm + 12480;
    float* xt_s = sm + 16640;
    float* kt_s = xt_s + 64;
    float* m_s  = kt_s + 64;
    float* l_s  = m_s + 64;
    float* f_s  = l_s + 64;
    __shared__ int rng[2];

    const int tid = threadIdx.x;
    const int ty = tid >> 4, tx = tid & 15;
    const int q0 = blockIdx.x * 64;
    const int h  = blockIdx.y;
    const int b  = blockIdx.z;
    const float distf = (float)p_dist[0];
    const float mindf = (float)p_mind[0];

    const float* Qg = g_q + ((size_t)(b * HH + h) * TX + q0) * DD;
    const float* Kg = g_k + (size_t)(b * HH + h) * TY * DD;
    const float* Vg = g_v + (size_t)(b * HH + h) * TY * DD;
    const float* Y  = yt + (size_t)b * TY;

    for (int idx = tid; idx < 64 * 64; idx += 256) {
        int r = idx >> 6, d = idx & 63;
        q_s[r * 65 + d] = Qg[r * DD + d];
    }
    if (tid < 64) {
        xt_s[tid] = xt[(size_t)b * TX + q0 + tid] - mindf;
        m_s[tid] = -1e30f;
        l_s[tid] = 0.f;
    }
    if (tid == 0) {
        float xmin = xt[(size_t)b * TX + q0] - mindf;
        float xmax = xt[(size_t)b * TX + q0 + 63] - mindf;
        int lo = 0, hi = TY;
        while (lo < hi) { int mid = (lo + hi) >> 1; if (Y[mid] >= xmin - distf) hi = mid; else lo = mid + 1; }
        rng[0] = lo & ~63;
        lo = 0; hi = TY;
        while (lo < hi) { int mid = (lo + hi) >> 1; if (Y[mid] > xmax) hi = mid; else lo = mid + 1; }
        rng[1] = lo;
    }
    __syncthreads();
    const int ks = rng[0], ke = rng[1];

    float o[4][4];
#pragma unroll
    for (int i = 0; i < 4; i++)
#pragma unroll
        for (int j = 0; j < 4; j++) o[i][j] = 0.f;

    for (int kb = ks; kb < ke; kb += 64) {
        for (int idx = tid; idx < 64 * 64; idx += 256) {
            int c = idx >> 6, d = idx & 63;
            int gi = kb + c;
            float kv = 0.f, vv = 0.f;
            if (gi < TY) { kv = Kg[(size_t)gi * DD + d]; vv = Vg[(size_t)gi * DD + d]; }
            k_s[c * 65 + d] = kv;
            v_s[c * 65 + d] = vv;
        }
        if (tid < 64) kt_s[tid] = (kb + tid < TY) ? Y[kb + tid] : 3e38f;
        __syncthreads();

        float acc[4][4];
#pragma unroll
        for (int i = 0; i < 4; i++)
#pragma unroll
            for (int j = 0; j < 4; j++) acc[i][j] = 0.f;
#pragma unroll 16
        for (int d = 0; d < 64; d++) {
            float a4[4], b4[4];
#pragma unroll
            for (int i = 0; i < 4; i++) a4[i] = q_s[(ty * 4 + i) * 65 + d];
#pragma unroll
            for (int j = 0; j < 4; j++) b4[j] = k_s[(tx * 4 + j) * 65 + d];
#pragma unroll
            for (int i = 0; i < 4; i++)
#pragma unroll
                for (int j = 0; j < 4; j++) acc[i][j] = fmaf(a4[i], b4[j], acc[i][j]);
        }
#pragma unroll
        for (int i = 0; i < 4; i++) {
            int r = ty * 4 + i;
            float xv = xt_s[r];
#pragma unroll
            for (int j = 0; j < 4; j++) {
                int c = tx * 4 + j;
                float yv = kt_s[c];
                bool ok = (xv >= yv) && (xv <= yv + distf);
                s_s[r * 65 + c] = ok ? acc[i][j] * 0.125f : -1e30f;
            }
        }
        __syncthreads();

        {
            int row = tid >> 2, jj = tid & 3;
            int c0 = jj * 16;
            float mx = -1e30f;
#pragma unroll
            for (int c = 0; c < 16; c++) mx = fmaxf(mx, s_s[row * 65 + c0 + c]);
            mx = fmaxf(mx, __shfl_xor_sync(0xffffffffu, mx, 1));
            mx = fmaxf(mx, __shfl_xor_sync(0xffffffffu, mx, 2));
            float m_old = m_s[row];
            float m_new = fmaxf(m_old, mx);
            float sum = 0.f;
#pragma unroll
            for (int c = 0; c < 16; c++) {
                float sv = s_s[row * 65 + c0 + c];
                float pv = (sv <= -1e29f) ? 0.f : __expf(sv - m_new);
                s_s[row * 65 + c0 + c] = pv;
                sum += pv;
            }
            sum += __shfl_xor_sync(0xffffffffu, sum, 1);
            sum += __shfl_xor_sync(0xffffffffu, sum, 2);
            if (jj == 0) {
                float fct = __expf(m_old - m_new);
                l_s[row] = l_s[row] * fct + sum;
                m_s[row] = m_new;
                f_s[row] = fct;
            }
        }
        __syncthreads();

        float fct[4];
#pragma unroll
        for (int i = 0; i < 4; i++) fct[i] = f_s[ty * 4 + i];
#pragma unroll
        for (int i = 0; i < 4; i++)
#pragma unroll
            for (int j = 0; j < 4; j++) o[i][j] *= fct[i];
#pragma unroll 16
        for (int c = 0; c < 64; c++) {
            float p4[4], v4[4];
#pragma unroll
            for (int i = 0; i < 4; i++) p4[i] = s_s[(ty * 4 + i) * 65 + c];
#pragma unroll
            for (int j = 0; j < 4; j++) v4[j] = v_s[c * 65 + tx * 4 + j];
#pragma unroll
            for (int i = 0; i < 4; i++)
#pragma unroll
                for (int j = 0; j < 4; j++) o[i][j] = fmaf(p4[i], v4[j], o[i][j]);
        }
        __syncthreads();
    }

#pragma unroll
    for (int i = 0; i < 4; i++) {
        int r = ty * 4 + i;
        float l = l_s[r];
        float rcp = (l > 0.f) ? 1.f / l : 0.f;
#pragma unroll
        for (int j = 0; j < 4; j++)
            g_o[((size_t)b * TX + q0 + r) * CC + h * DD + tx * 4 + j] = o[i][j] * rcp;
    }
}

extern "C" void kernel_launch(void* const* d_in, const int* in_sizes, int n_in,
                              void* d_out, int out_size) {
    const float* x    = (const float*)d_in[0];
    const float* x_t  = (const float*)d_in[1];
    const float* y    = (const float*)d_in[2];
    const float* y_t  = (const float*)d_in[3];
    const int*   dist = (const int*)d_in[4];
    const int*   mind = (const int*)d_in[5];
    const float* Wq   = (const float*)d_in[6];
    const float* Wkv  = (const float*)d_in[7];
    const float* Wpr  = (const float*)d_in[8];
    const float* invf = (const float*)d_in[9];
    float* out = (float*)d_out;

    __nv_bfloat16 *p_gx_hi, *p_gx_lo, *p_gy_hi, *p_gy_lo, *p_go_hi, *p_go_lo;
    __nv_bfloat16 *p_wq_hi, *p_wq_lo, *p_wkv_hi, *p_wkv_lo, *p_wp_hi, *p_wp_lo;
    float *p_go;
    cudaGetSymbolAddress((void**)&p_gx_hi, gx_hi);
    cudaGetSymbolAddress((void**)&p_gx_lo, gx_lo);
    cudaGetSymbolAddress((void**)&p_gy_hi, gy_hi);
    cudaGetSymbolAddress((void**)&p_gy_lo, gy_lo);
    cudaGetSymbolAddress((void**)&p_go_hi, go_hi);
    cudaGetSymbolAddress((void**)&p_go_lo, go_lo);
    cudaGetSymbolAddress((void**)&p_wq_hi, gwq_hi);
    cudaGetSymbolAddress((void**)&p_wq_lo, gwq_lo);
    cudaGetSymbolAddress((void**)&p_wkv_hi, gwkv_hi);
    cudaGetSymbolAddress((void**)&p_wkv_lo, gwkv_lo);
    cudaGetSymbolAddress((void**)&p_wp_hi, gwp_hi);
    cudaGetSymbolAddress((void**)&p_wp_lo, gwp_lo);
    cudaGetSymbolAddress((void**)&p_go, g_o);

    cudaFuncSetAttribute(gemm_mma<0>, cudaFuncAttributeMaxDynamicSharedMemorySize, GEMM_SMEM);
    cudaFuncSetAttribute(gemm_mma<1>, cudaFuncAttributeMaxDynamicSharedMemorySize, GEMM_SMEM);
    cudaFuncSetAttribute(gemm_mma<2>, cudaFuncAttributeMaxDynamicSharedMemorySize, GEMM_SMEM);

    // prep: splits + weight transposes
    fsplit<<<(Bz * TX * CC / 4 + 255) / 256, 256>>>(x, p_gx_hi, p_gx_lo, Bz * TX * CC / 4);
    fsplit<<<(Bz * TY * CC / 4 + 255) / 256, 256>>>(y, p_gy_hi, p_gy_lo, Bz * TY * CC / 4);
    wtrans<<<dim3(CC / 32, CC / 32), 256>>>(Wq, p_wq_hi, p_wq_lo, CC, CC);
    wtrans<<<dim3(2 * CC / 32, CC / 32), 256>>>(Wkv, p_wkv_hi, p_wkv_lo, CC, 2 * CC);
    wtrans<<<dim3(CC / 32, CC / 32), 256>>>(Wpr, p_wp_hi, p_wp_lo, CC, CC);

    // q = rope(x @ Wq)
    gemm_mma<0><<<dim3(CC / 128, (Bz * TX) / 128), 256, GEMM_SMEM>>>(
        p_gx_hi, p_gx_lo, p_wq_hi, p_wq_lo, nullptr, Bz * TX, CC, CC, x_t, invf);
    // kv = y @ Wkv ; k = rope(kv[:, :C]) ; v = kv[:, C:]
    gemm_mma<1><<<dim3(2 * CC / 128, (Bz * TY) / 128), 256, GEMM_SMEM>>>(
        p_gy_hi, p_gy_lo, p_wkv_hi, p_wkv_lo, nullptr, Bz * TY, 2 * CC, CC, y_t, invf);
    // windowed flash attention
    const int smem_bytes = 16960 * 4;
    cudaFuncSetAttribute(flash_kernel, cudaFuncAttributeMaxDynamicSharedMemorySize, smem_bytes);
    flash_kernel<<<dim3(TX / 64, HH, Bz), 256, smem_bytes>>>(x_t, y_t, dist, mind);
    // split attention output, then out = o @ Wproj
    fsplit<<<(Bz * TX * CC / 4 + 255) / 256, 256>>>(p_go, p_go_hi, p_go_lo, Bz * TX * CC / 4);
    gemm_mma<2><<<dim3(CC / 128, (Bz * TX) / 128), 256, GEMM_SMEM>>>(
        p_go_hi, p_go_lo, p_wp_hi, p_wp_lo, out, Bz * TX, CC, CC, nullptr, nullptr);
}

// round 7
// speedup vs baseline: 2.3588x; 1.2901x over previous
#include <cuda_runtime.h>
#include <cuda_bf16.h>
#include <math.h>
#include <stdint.h>

#define Bz 2
#define TX 1024
#define TY 4096
#define CC 768
#define HH 12
#define DD 64

// bf16 hi/lo splits of activations ([M][K] row-major)
__device__ __nv_bfloat16 gx_hi[(size_t)Bz * TX * CC];
__device__ __nv_bfloat16 gx_lo[(size_t)Bz * TX * CC];
__device__ __nv_bfloat16 gy_hi[(size_t)Bz * TY * CC];
__device__ __nv_bfloat16 gy_lo[(size_t)Bz * TY * CC];
__device__ __nv_bfloat16 go_hi[(size_t)Bz * TX * CC];
__device__ __nv_bfloat16 go_lo[(size_t)Bz * TX * CC];
// transposed weights [N][K] bf16 hi/lo
__device__ __nv_bfloat16 gwq_hi[(size_t)CC * CC];
__device__ __nv_bfloat16 gwq_lo[(size_t)CC * CC];
__device__ __nv_bfloat16 gwkv_hi[(size_t)2 * CC * CC];
__device__ __nv_bfloat16 gwkv_lo[(size_t)2 * CC * CC];
__device__ __nv_bfloat16 gwp_hi[(size_t)CC * CC];
__device__ __nv_bfloat16 gwp_lo[(size_t)CC * CC];
// attention operands, bf16 hi/lo planes
__device__ __nv_bfloat16 q_hi[(size_t)Bz * HH * TX * DD];
__device__ __nv_bfloat16 q_lo[(size_t)Bz * HH * TX * DD];
__device__ __nv_bfloat16 k_hi[(size_t)Bz * HH * TY * DD];
__device__ __nv_bfloat16 k_lo[(size_t)Bz * HH * TY * DD];
__device__ __nv_bfloat16 vt_hi[(size_t)Bz * HH * DD * TY];  // [b,h,d,t]
__device__ __nv_bfloat16 vt_lo[(size_t)Bz * HH * DD * TY];

__device__ __forceinline__ void split_bf16(float x, __nv_bfloat16& h, __nv_bfloat16& l) {
    h = __float2bfloat16(x);
    l = __float2bfloat16(x - __bfloat162float(h));
}
__device__ __forceinline__ uint32_t pack_bf(__nv_bfloat16 a, __nv_bfloat16 b) {
    uint16_t ua = *reinterpret_cast<uint16_t*>(&a);
    uint16_t ub = *reinterpret_cast<uint16_t*>(&b);
    return (uint32_t)ua | ((uint32_t)ub << 16);
}
// split a float pair into packed hi / packed lo
__device__ __forceinline__ void split_pack(float a, float b, uint32_t& hp, uint32_t& lp) {
    __nv_bfloat16 h0, l0, h1, l1;
    split_bf16(a, h0, l0);
    split_bf16(b, h1, l1);
    hp = pack_bf(h0, h1);
    lp = pack_bf(l0, l1);
}

// ---------------------------------------------------------------------------
// Prep kernels
// ---------------------------------------------------------------------------
__global__ void __launch_bounds__(256)
fsplit(const float* __restrict__ A, __nv_bfloat16* __restrict__ hi,
       __nv_bfloat16* __restrict__ lo, int n4)
{
    int i = blockIdx.x * 256 + threadIdx.x;
    if (i >= n4) return;
    float4 v = ((const float4*)A)[i];
    __nv_bfloat16 h[4], l[4];
    split_bf16(v.x, h[0], l[0]); split_bf16(v.y, h[1], l[1]);
    split_bf16(v.z, h[2], l[2]); split_bf16(v.w, h[3], l[3]);
    ((uint2*)hi)[i] = *(uint2*)h;
    ((uint2*)lo)[i] = *(uint2*)l;
}

__global__ void __launch_bounds__(256)
wtrans(const float* __restrict__ W, __nv_bfloat16* __restrict__ Thi,
       __nv_bfloat16* __restrict__ Tlo, int K, int N)
{
    __shared__ float sm[32][33];
    int n0 = blockIdx.x * 32, k0 = blockIdx.y * 32;
    int tx = threadIdx.x & 31, ty = threadIdx.x >> 5;
#pragma unroll
    for (int i = 0; i < 4; i++)
        sm[ty + 8 * i][tx] = W[(size_t)(k0 + ty + 8 * i) * N + n0 + tx];
    __syncthreads();
#pragma unroll
    for (int i = 0; i < 4; i++) {
        float v = sm[tx][ty + 8 * i];
        __nv_bfloat16 h, l;
        split_bf16(v, h, l);
        size_t o = (size_t)(n0 + ty + 8 * i) * K + k0 + tx;
        Thi[o] = h;
        Tlo[o] = l;
    }
}

// ---------------------------------------------------------------------------
// HMMA GEMM: C[M,N]=A[M,K]@W[K,N], bf16x3 split, m16n8k16. Tile 128x128.
// MODE 0: RoPE -> q_hi/lo   MODE 1: K(RoPE)->k_hi/lo, V->vt_hi/lo   MODE 2: -> Out fp32
// ---------------------------------------------------------------------------
#define SA_HI 0u
#define SA_LO 16384u
#define SB_HI 32768u
#define SB_LO 49152u
#define GEMM_SMEM 65536u

__device__ __forceinline__ void mma16816(float* c, const uint32_t* a, const uint32_t* b) {
    asm volatile(
        "mma.sync.aligned.m16n8k16.row.col.f32.bf16.bf16.f32 "
        "{%0,%1,%2,%3},{%4,%5,%6,%7},{%8,%9},{%0,%1,%2,%3};"
        : "+f"(c[0]), "+f"(c[1]), "+f"(c[2]), "+f"(c[3])
        : "r"(a[0]), "r"(a[1]), "r"(a[2]), "r"(a[3]), "r"(b[0]), "r"(b[1]));
}

template <int MODE>
__global__ void __launch_bounds__(256, 2)
gemm_mma(const __nv_bfloat16* __restrict__ Ahi, const __nv_bfloat16* __restrict__ Alo,
         const __nv_bfloat16* __restrict__ Bhi, const __nv_bfloat16* __restrict__ Blo,
         float* __restrict__ Out, int M, int N, int K,
         const float* __restrict__ tvec, const float* __restrict__ invf)
{
    extern __shared__ __align__(16) uint8_t smem[];
    const int tid = threadIdx.x;
    const int wid = tid >> 5, lane = tid & 31;
    const int wm = wid & 1, wn = wid >> 1;
    const int m0 = blockIdx.y * 128, n0 = blockIdx.x * 128;
    const int lr = lane >> 2, lc = lane & 3;

    float acc[4][4][4];
#pragma unroll
    for (int a = 0; a < 4; a++)
#pragma unroll
        for (int b = 0; b < 4; b++)
#pragma unroll
            for (int c = 0; c < 4; c++) acc[a][b][c] = 0.f;

    const int NCH = K / 64;
    for (int ch = 0; ch < NCH; ch++) {
        const int k0 = ch * 64;
#pragma unroll
        for (int it = 0; it < 4; it++) {
            int i = tid + it * 256;
            int r = i >> 3, t = i & 7;
            uint32_t soff = (uint32_t)(r * 128 + ((t ^ (r & 7)) << 4));
            size_t ga = (size_t)(m0 + r) * K + k0 + t * 8;
            *(uint4*)(smem + SA_HI + soff) = *(const uint4*)(Ahi + ga);
            *(uint4*)(smem + SA_LO + soff) = *(const uint4*)(Alo + ga);
            size_t gb = (size_t)(n0 + r) * K + k0 + t * 8;
            *(uint4*)(smem + SB_HI + soff) = *(const uint4*)(Bhi + gb);
            *(uint4*)(smem + SB_LO + soff) = *(const uint4*)(Blo + gb);
        }
        __syncthreads();

#pragma unroll
        for (int s = 0; s < 4; s++) {
            uint32_t bh[4][2], bl[4][2];
#pragma unroll
            for (int nt = 0; nt < 4; nt++) {
                int n = wn * 32 + nt * 8 + lr;
                uint32_t base = (uint32_t)(n * 128) + 4u * lc;
                uint32_t g0 = (uint32_t)(((2 * s) ^ (n & 7)) << 4);
                uint32_t g1 = (uint32_t)(((2 * s + 1) ^ (n & 7)) << 4);
                bh[nt][0] = *(uint32_t*)(smem + SB_HI + base + g0);
                bh[nt][1] = *(uint32_t*)(smem + SB_HI + base + g1);
                bl[nt][0] = *(uint32_t*)(smem + SB_LO + base + g0);
                bl[nt][1] = *(uint32_t*)(smem + SB_LO + base + g1);
            }
#pragma unroll
            for (int mt = 0; mt < 4; mt++) {
                int m1 = wm * 64 + mt * 16 + lr;
                int m2 = m1 + 8;
                uint32_t b1 = (uint32_t)(m1 * 128) + 4u * lc;
                uint32_t b2 = (uint32_t)(m2 * 128) + 4u * lc;
                uint32_t g10 = (uint32_t)(((2 * s) ^ (m1 & 7)) << 4);
                uint32_t g11 = (uint32_t)(((2 * s + 1) ^ (m1 & 7)) << 4);
                uint32_t g20 = (uint32_t)(((2 * s) ^ (m2 & 7)) << 4);
                uint32_t g21 = (uint32_t)(((2 * s + 1) ^ (m2 & 7)) << 4);
                uint32_t ah[4], al[4];
                ah[0] = *(uint32_t*)(smem + SA_HI + b1 + g10);
                ah[1] = *(uint32_t*)(smem + SA_HI + b2 + g20);
                ah[2] = *(uint32_t*)(smem + SA_HI + b1 + g11);
                ah[3] = *(uint32_t*)(smem + SA_HI + b2 + g21);
                al[0] = *(uint32_t*)(smem + SA_LO + b1 + g10);
                al[1] = *(uint32_t*)(smem + SA_LO + b2 + g20);
                al[2] = *(uint32_t*)(smem + SA_LO + b1 + g11);
                al[3] = *(uint32_t*)(smem + SA_LO + b2 + g21);
#pragma unroll
                for (int nt = 0; nt < 4; nt++) {
                    mma16816(acc[mt][nt], ah, bh[nt]);
                    mma16816(acc[mt][nt], ah, bl[nt]);
                    mma16816(acc[mt][nt], al, bh[nt]);
                }
            }
        }
        __syncthreads();
    }

    // ---- epilogue ----
#pragma unroll
    for (int mt = 0; mt < 4; mt++) {
        int mA = m0 + wm * 64 + mt * 16 + lr;
#pragma unroll
        for (int half = 0; half < 2; half++) {
            int m = mA + half * 8;
            float pos = 0.f;
            int bb = 0, tt = 0;
            if (MODE == 0) { bb = m / TX; tt = m % TX; pos = tvec[m]; }
            if (MODE == 1) { bb = m / TY; tt = m % TY; pos = tvec[m]; }
#pragma unroll
            for (int nt = 0; nt < 4; nt++) {
                float c0 = acc[mt][nt][half * 2 + 0];
                float c1 = acc[mt][nt][half * 2 + 1];
                int col = n0 + wn * 32 + nt * 8 + 2 * lc;
                if (MODE == 2) {
                    *(float2*)&Out[(size_t)m * N + col] = make_float2(c0, c1);
                } else if (MODE == 0) {
                    int h = col / DD, dd = col % DD;
                    float f = pos * invf[dd >> 1];
                    float sn, cs;
                    sincosf(f, &sn, &cs);
                    uint32_t hp, lp;
                    split_pack(c0 * cs - c1 * sn, c1 * cs + c0 * sn, hp, lp);
                    size_t idx = ((size_t)(bb * HH + h) * TX + tt) * DD + dd;
                    *(uint32_t*)&q_hi[idx] = hp;
                    *(uint32_t*)&q_lo[idx] = lp;
                } else {
                    if (col < CC) {
                        int h = col / DD, dd = col % DD;
                        float f = pos * invf[dd >> 1];
                        float sn, cs;
                        sincosf(f, &sn, &cs);
                        uint32_t hp, lp;
                        split_pack(c0 * cs - c1 * sn, c1 * cs + c0 * sn, hp, lp);
                        size_t idx = ((size_t)(bb * HH + h) * TY + tt) * DD + dd;
                        *(uint32_t*)&k_hi[idx] = hp;
                        *(uint32_t*)&k_lo[idx] = lp;
                    } else {
                        int nv = col - CC;
                        int h = nv / DD, dd = nv % DD;
                        __nv_bfloat16 h0, l0, h1, l1;
                        split_bf16(c0, h0, l0);
                        split_bf16(c1, h1, l1);
                        size_t i0 = ((size_t)(bb * HH + h) * DD + dd) * TY + tt;
                        vt_hi[i0] = h0;      vt_lo[i0] = l0;
                        vt_hi[i0 + TY] = h1; vt_lo[i0 + TY] = l1;
                    }
                }
            }
        }
    }
}

// ---------------------------------------------------------------------------
// Flash attention with HMMA. Grid (TX/64, H, B), 128 threads (4 warps x 16 rows).
// Q frags in registers; K/VT tiles in smem (swizzled like the GEMM).
// S = QK^T and O += P V both via bf16x3-split m16n8k16.
// ---------------------------------------------------------------------------
#define FL_SKHI 0u
#define FL_SKLO 8192u
#define FL_SVHI 16384u
#define FL_SVLO 24576u
#define FL_SKT  32768u
#define FL_RNG  33024u
#define FL_SMEM 33056u

__global__ void __launch_bounds__(128)
flash_mma(const float* __restrict__ xt, const float* __restrict__ yt,
          const int* __restrict__ p_dist, const int* __restrict__ p_mind)
{
    extern __shared__ __align__(16) uint8_t sm[];
    float* kt_s = (float*)(sm + FL_SKT);
    int* rng = (int*)(sm + FL_RNG);

    const int tid = threadIdx.x;
    const int wid = tid >> 5, lane = tid & 31;
    const int lr = lane >> 2, lc = lane & 3;
    const int q0 = blockIdx.x * 64;
    const int h = blockIdx.y, b = blockIdx.z;
    const float distf = (float)p_dist[0];
    const float mindf = (float)p_mind[0];
    const size_t bh = (size_t)(b * HH + h);

    const __nv_bfloat16* Qh = q_hi + bh * TX * DD;
    const __nv_bfloat16* Ql = q_lo + bh * TX * DD;
    const __nv_bfloat16* Kh = k_hi + bh * TY * DD;
    const __nv_bfloat16* Kl = k_lo + bh * TY * DD;
    const __nv_bfloat16* Vh = vt_hi + bh * DD * TY;
    const __nv_bfloat16* Vl = vt_lo + bh * DD * TY;
    const float* Y = yt + (size_t)b * TY;

    const int r0 = q0 + wid * 16 + lr;
    const int r1 = r0 + 8;

    // Q fragments (resident across the whole key loop)
    uint32_t qh[4][4], ql[4][4];
#pragma unroll
    for (int ks2 = 0; ks2 < 4; ks2++) {
        qh[ks2][0] = *(const uint32_t*)&Qh[(size_t)r0 * DD + 16 * ks2 + 2 * lc];
        qh[ks2][1] = *(const uint32_t*)&Qh[(size_t)r1 * DD + 16 * ks2 + 2 * lc];
        qh[ks2][2] = *(const uint32_t*)&Qh[(size_t)r0 * DD + 16 * ks2 + 8 + 2 * lc];
        qh[ks2][3] = *(const uint32_t*)&Qh[(size_t)r1 * DD + 16 * ks2 + 8 + 2 * lc];
        ql[ks2][0] = *(const uint32_t*)&Ql[(size_t)r0 * DD + 16 * ks2 + 2 * lc];
        ql[ks2][1] = *(const uint32_t*)&Ql[(size_t)r1 * DD + 16 * ks2 + 2 * lc];
        ql[ks2][2] = *(const uint32_t*)&Ql[(size_t)r0 * DD + 16 * ks2 + 8 + 2 * lc];
        ql[ks2][3] = *(const uint32_t*)&Ql[(size_t)r1 * DD + 16 * ks2 + 8 + 2 * lc];
    }
    const float xr0 = xt[(size_t)b * TX + r0] - mindf;
    const float xr1 = xt[(size_t)b * TX + r1] - mindf;

    if (tid == 0) {
        float xmin = xt[(size_t)b * TX + q0] - mindf;
        float xmax = xt[(size_t)b * TX + q0 + 63] - mindf;
        int lo = 0, hi = TY;
        while (lo < hi) { int mid = (lo + hi) >> 1; if (Y[mid] >= xmin - distf) hi = mid; else lo = mid + 1; }
        rng[0] = lo & ~63;
        lo = 0; hi = TY;
        while (lo < hi) { int mid = (lo + hi) >> 1; if (Y[mid] > xmax) hi = mid; else lo = mid + 1; }
        rng[1] = lo;
    }
    __syncthreads();
    const int ksr = rng[0], ker = rng[1];

    float m0r = -1e30f, m1r = -1e30f, l0r = 0.f, l1r = 0.f;
    float o[8][4];
#pragma unroll
    for (int i = 0; i < 8; i++)
#pragma unroll
        for (int j = 0; j < 4; j++) o[i][j] = 0.f;

    for (int kb = ksr; kb < ker; kb += 64) {
        // ---- fill K/VT tiles (swizzled rows of 128B) ----
#pragma unroll
        for (int it = 0; it < 4; it++) {
            int i = tid + it * 128;
            int r = i >> 3, t = i & 7;
            uint32_t so = (uint32_t)(r * 128 + ((t ^ (r & 7)) << 4));
            size_t gk = (size_t)(kb + r) * DD + t * 8;
            *(uint4*)(sm + FL_SKHI + so) = *(const uint4*)(Kh + gk);
            *(uint4*)(sm + FL_SKLO + so) = *(const uint4*)(Kl + gk);
            size_t gv = (size_t)r * TY + kb + t * 8;
            *(uint4*)(sm + FL_SVHI + so) = *(const uint4*)(Vh + gv);
            *(uint4*)(sm + FL_SVLO + so) = *(const uint4*)(Vl + gv);
        }
        if (tid < 64) kt_s[tid] = Y[kb + tid];
        __syncthreads();

        // ---- S = Q K^T ----
        float s[8][4];
#pragma unroll
        for (int i = 0; i < 8; i++)
#pragma unroll
            for (int j = 0; j < 4; j++) s[i][j] = 0.f;
#pragma unroll
        for (int ks2 = 0; ks2 < 4; ks2++) {
#pragma unroll
            for (int nt = 0; nt < 8; nt++) {
                int n = nt * 8 + lr;
                uint32_t base = (uint32_t)(n * 128) + 4u * lc;
                uint32_t g0 = (uint32_t)(((2 * ks2) ^ (n & 7)) << 4);
                uint32_t g1 = (uint32_t)(((2 * ks2 + 1) ^ (n & 7)) << 4);
                uint32_t bhh[2] = {*(uint32_t*)(sm + FL_SKHI + base + g0),
                                   *(uint32_t*)(sm + FL_SKHI + base + g1)};
                uint32_t bll[2] = {*(uint32_t*)(sm + FL_SKLO + base + g0),
                                   *(uint32_t*)(sm + FL_SKLO + base + g1)};
                mma16816(s[nt], qh[ks2], bhh);
                mma16816(s[nt], qh[ks2], bll);
                mma16816(s[nt], ql[ks2], bhh);
            }
        }

        // ---- mask + scale ----
#pragma unroll
        for (int nt = 0; nt < 8; nt++) {
#pragma unroll
            for (int j = 0; j < 2; j++) {
                float yv = kt_s[nt * 8 + 2 * lc + j];
                bool ok0 = (xr0 >= yv) && (xr0 <= yv + distf);
                bool ok1 = (xr1 >= yv) && (xr1 <= yv + distf);
                s[nt][j]     = ok0 ? s[nt][j] * 0.125f     : -1e30f;
                s[nt][j + 2] = ok1 ? s[nt][j + 2] * 0.125f : -1e30f;
            }
        }
        // ---- online softmax (quad shfl; rows lr / lr+8 of this warp) ----
        float mx0 = -1e30f, mx1 = -1e30f;
#pragma unroll
        for (int nt = 0; nt < 8; nt++) {
            mx0 = fmaxf(mx0, fmaxf(s[nt][0], s[nt][1]));
            mx1 = fmaxf(mx1, fmaxf(s[nt][2], s[nt][3]));
        }
        mx0 = fmaxf(mx0, __shfl_xor_sync(0xffffffffu, mx0, 1));
        mx0 = fmaxf(mx0, __shfl_xor_sync(0xffffffffu, mx0, 2));
        mx1 = fmaxf(mx1, __shfl_xor_sync(0xffffffffu, mx1, 1));
        mx1 = fmaxf(mx1, __shfl_xor_sync(0xffffffffu, mx1, 2));
        float mn0 = fmaxf(m0r, mx0), mn1 = fmaxf(m1r, mx1);
        float f0 = __expf(m0r - mn0), f1 = __expf(m1r - mn1);

        uint32_t ph[8][2], pl[8][2];
        float sum0 = 0.f, sum1 = 0.f;
#pragma unroll
        for (int nt = 0; nt < 8; nt++) {
            float p00 = (s[nt][0] <= -1e29f) ? 0.f : __expf(s[nt][0] - mn0);
            float p01 = (s[nt][1] <= -1e29f) ? 0.f : __expf(s[nt][1] - mn0);
            float p10 = (s[nt][2] <= -1e29f) ? 0.f : __expf(s[nt][2] - mn1);
            float p11 = (s[nt][3] <= -1e29f) ? 0.f : __expf(s[nt][3] - mn1);
            sum0 += p00 + p01;
            sum1 += p10 + p11;
            split_pack(p00, p01, ph[nt][0], pl[nt][0]);
            split_pack(p10, p11, ph[nt][1], pl[nt][1]);
        }
        sum0 += __shfl_xor_sync(0xffffffffu, sum0, 1);
        sum0 += __shfl_xor_sync(0xffffffffu, sum0, 2);
        sum1 += __shfl_xor_sync(0xffffffffu, sum1, 1);
        sum1 += __shfl_xor_sync(0xffffffffu, sum1, 2);
        l0r = l0r * f0 + sum0;
        l1r = l1r * f1 + sum1;
        m0r = mn0;
        m1r = mn1;
#pragma unroll
        for (int nd = 0; nd < 8; nd++) {
            o[nd][0] *= f0; o[nd][1] *= f0;
            o[nd][2] *= f1; o[nd][3] *= f1;
        }

        // ---- O += P V ----
#pragma unroll
        for (int kp = 0; kp < 4; kp++) {
            uint32_t ah[4] = {ph[2 * kp][0], ph[2 * kp][1], ph[2 * kp + 1][0], ph[2 * kp + 1][1]};
            uint32_t al[4] = {pl[2 * kp][0], pl[2 * kp][1], pl[2 * kp + 1][0], pl[2 * kp + 1][1]};
#pragma unroll
            for (int nd = 0; nd < 8; nd++) {
                int n = nd * 8 + lr;
                uint32_t base = (uint32_t)(n * 128) + 4u * lc;
                uint32_t g0 = (uint32_t)(((2 * kp) ^ (n & 7)) << 4);
                uint32_t g1 = (uint32_t)(((2 * kp + 1) ^ (n & 7)) << 4);
                uint32_t bvh[2] = {*(uint32_t*)(sm + FL_SVHI + base + g0),
                                   *(uint32_t*)(sm + FL_SVHI + base + g1)};
                uint32_t bvl[2] = {*(uint32_t*)(sm + FL_SVLO + base + g0),
                                   *(uint32_t*)(sm + FL_SVLO + base + g1)};
                mma16816(o[nd], ah, bvh);
                mma16816(o[nd], ah, bvl);
                mma16816(o[nd], al, bvh);
            }
        }
        __syncthreads();
    }

    // ---- epilogue: O/l -> go_hi/go_lo bf16 splits ----
    float rc0 = (l0r > 0.f) ? 1.f / l0r : 0.f;
    float rc1 = (l1r > 0.f) ? 1.f / l1r : 0.f;
#pragma unroll
    for (int nd = 0; nd < 8; nd++) {
        int d0 = nd * 8 + 2 * lc;
        uint32_t hp, lp;
        size_t i0 = ((size_t)b * TX + r0) * CC + h * DD + d0;
        split_pack(o[nd][0] * rc0, o[nd][1] * rc0, hp, lp);
        *(uint32_t*)&go_hi[i0] = hp;
        *(uint32_t*)&go_lo[i0] = lp;
        size_t i1 = ((size_t)b * TX + r1) * CC + h * DD + d0;
        split_pack(o[nd][2] * rc1, o[nd][3] * rc1, hp, lp);
        *(uint32_t*)&go_hi[i1] = hp;
        *(uint32_t*)&go_lo[i1] = lp;
    }
}

extern "C" void kernel_launch(void* const* d_in, const int* in_sizes, int n_in,
                              void* d_out, int out_size) {
    const float* x    = (const float*)d_in[0];
    const float* x_t  = (const float*)d_in[1];
    const float* y    = (const float*)d_in[2];
    const float* y_t  = (const float*)d_in[3];
    const int*   dist = (const int*)d_in[4];
    const int*   mind = (const int*)d_in[5];
    const float* Wq   = (const float*)d_in[6];
    const float* Wkv  = (const float*)d_in[7];
    const float* Wpr  = (const float*)d_in[8];
    const float* invf = (const float*)d_in[9];
    float* out = (float*)d_out;

    __nv_bfloat16 *p_gx_hi, *p_gx_lo, *p_gy_hi, *p_gy_lo, *p_go_hi, *p_go_lo;
    __nv_bfloat16 *p_wq_hi, *p_wq_lo, *p_wkv_hi, *p_wkv_lo, *p_wp_hi, *p_wp_lo;
    cudaGetSymbolAddress((void**)&p_gx_hi, gx_hi);
    cudaGetSymbolAddress((void**)&p_gx_lo, gx_lo);
    cudaGetSymbolAddress((void**)&p_gy_hi, gy_hi);
    cudaGetSymbolAddress((void**)&p_gy_lo, gy_lo);
    cudaGetSymbolAddress((void**)&p_go_hi, go_hi);
    cudaGetSymbolAddress((void**)&p_go_lo, go_lo);
    cudaGetSymbolAddress((void**)&p_wq_hi, gwq_hi);
    cudaGetSymbolAddress((void**)&p_wq_lo, gwq_lo);
    cudaGetSymbolAddress((void**)&p_wkv_hi, gwkv_hi);
    cudaGetSymbolAddress((void**)&p_wkv_lo, gwkv_lo);
    cudaGetSymbolAddress((void**)&p_wp_hi, gwp_hi);
    cudaGetSymbolAddress((void**)&p_wp_lo, gwp_lo);

    cudaFuncSetAttribute(gemm_mma<0>, cudaFuncAttributeMaxDynamicSharedMemorySize, GEMM_SMEM);
    cudaFuncSetAttribute(gemm_mma<1>, cudaFuncAttributeMaxDynamicSharedMemorySize, GEMM_SMEM);
    cudaFuncSetAttribute(gemm_mma<2>, cudaFuncAttributeMaxDynamicSharedMemorySize, GEMM_SMEM);
    cudaFuncSetAttribute(flash_mma, cudaFuncAttributeMaxDynamicSharedMemorySize, FL_SMEM);

    // prep: splits + weight transposes
    fsplit<<<(Bz * TX * CC / 4 + 255) / 256, 256>>>(x, p_gx_hi, p_gx_lo, Bz * TX * CC / 4);
    fsplit<<<(Bz * TY * CC / 4 + 255) / 256, 256>>>(y, p_gy_hi, p_gy_lo, Bz * TY * CC / 4);
    wtrans<<<dim3(CC / 32, CC / 32), 256>>>(Wq, p_wq_hi, p_wq_lo, CC, CC);
    wtrans<<<dim3(2 * CC / 32, CC / 32), 256>>>(Wkv, p_wkv_hi, p_wkv_lo, CC, 2 * CC);
    wtrans<<<dim3(CC / 32, CC / 32), 256>>>(Wpr, p_wp_hi, p_wp_lo, CC, CC);

    // q = rope(x @ Wq) -> q_hi/lo
    gemm_mma<0><<<dim3(CC / 128, (Bz * TX) / 128), 256, GEMM_SMEM>>>(
        p_gx_hi, p_gx_lo, p_wq_hi, p_wq_lo, nullptr, Bz * TX, CC, CC, x_t, invf);
    // kv = y @ Wkv -> k_hi/lo (RoPE), vt_hi/lo (transposed)
    gemm_mma<1><<<dim3(2 * CC / 128, (Bz * TY) / 128), 256, GEMM_SMEM>>>(
        p_gy_hi, p_gy_lo, p_wkv_hi, p_wkv_lo, nullptr, Bz * TY, 2 * CC, CC, y_t, invf);
    // windowed flash attention (HMMA) -> go_hi/lo
    flash_mma<<<dim3(TX / 64, HH, Bz), 128, FL_SMEM>>>(x_t, y_t, dist, mind);
    // out = o @ Wproj
    gemm_mma<2><<<dim3(CC / 128, (Bz * TX) / 128), 256, GEMM_SMEM>>>(
        p_go_hi, p_go_lo, p_wp_hi, p_wp_lo, out, Bz * TX, CC, CC, nullptr, nullptr);
}

// round 9
// speedup vs baseline: 5.7369x; 2.4322x over previous
#include <cuda_runtime.h>
#include <cuda_fp16.h>
#include <math.h>
#include <stdint.h>

#define Bz 2
#define TX 1024
#define TY 4096
#define CC 768
#define HH 12
#define DD 64

// fp16 activations ([M][K] row-major)
__device__ __half gx_h[(size_t)Bz * TX * CC];
__device__ __half gy_h[(size_t)Bz * TY * CC];
__device__ __half go_h[(size_t)Bz * TX * CC];
// transposed weights [N][K] fp16
__device__ __half gwq_h[(size_t)CC * CC];
__device__ __half gwkv_h[(size_t)2 * CC * CC];
__device__ __half gwp_h[(size_t)CC * CC];
// attention operands fp16
__device__ __half q_h[(size_t)Bz * HH * TX * DD];
__device__ __half k_h[(size_t)Bz * HH * TY * DD];
__device__ __half vt_h[(size_t)Bz * HH * DD * TY];  // [b,h,d,t]

__device__ __forceinline__ uint32_t pack_h2(float a, float b) {
    __half2 h = __floats2half2_rn(a, b);
    return *reinterpret_cast<uint32_t*>(&h);
}

__device__ __forceinline__ void cp16(uint32_t saddr, const void* g) {
    asm volatile("cp.async.cg.shared.global [%0], [%1], 16;" :: "r"(saddr), "l"(g));
}

__device__ __forceinline__ void mma_h(float* c, const uint32_t* a, const uint32_t* b) {
    asm volatile(
        "mma.sync.aligned.m16n8k16.row.col.f32.f16.f16.f32 "
        "{%0,%1,%2,%3},{%4,%5,%6,%7},{%8,%9},{%0,%1,%2,%3};"
        : "+f"(c[0]), "+f"(c[1]), "+f"(c[2]), "+f"(c[3])
        : "r"(a[0]), "r"(a[1]), "r"(a[2]), "r"(a[3]), "r"(b[0]), "r"(b[1]));
}

// ---------------------------------------------------------------------------
// Prep: fp32 -> fp16
// ---------------------------------------------------------------------------
__global__ void __launch_bounds__(256)
fcvt(const float* __restrict__ A, __half* __restrict__ O, int n4)
{
    int i = blockIdx.x * 256 + threadIdx.x;
    if (i >= n4) return;
    float4 v = ((const float4*)A)[i];
    ((uint2*)O)[i] = make_uint2(pack_h2(v.x, v.y), pack_h2(v.z, v.w));
}

// Prep: W[K][N] fp32 -> Wt [N][K] fp16
__global__ void __launch_bounds__(256)
wtrans(const float* __restrict__ W, __half* __restrict__ T, int K, int N)
{
    __shared__ float sm[32][33];
    int n0 = blockIdx.x * 32, k0 = blockIdx.y * 32;
    int tx = threadIdx.x & 31, ty = threadIdx.x >> 5;
#pragma unroll
    for (int i = 0; i < 4; i++)
        sm[ty + 8 * i][tx] = W[(size_t)(k0 + ty + 8 * i) * N + n0 + tx];
    __syncthreads();
#pragma unroll
    for (int i = 0; i < 4; i++)
        T[(size_t)(n0 + ty + 8 * i) * K + k0 + tx] = __float2half(sm[tx][ty + 8 * i]);
}

// ---------------------------------------------------------------------------
// fp16 HMMA GEMM: C[M,N]=A[M,K]@W[K,N], m16n8k16, CTA tile 128x128,
// 2-stage cp.async pipeline (32KB/stage).
// MODE 0: RoPE -> q_h   MODE 1: K(RoPE)->k_h, V->vt_h   MODE 2: -> Out fp32
// ---------------------------------------------------------------------------
#define STG_SZ 32768u
#define GEMM_SMEM 65536u

template <int MODE>
__global__ void __launch_bounds__(256, 2)
gemm_mma(const __half* __restrict__ Ah, const __half* __restrict__ Bh,
         float* __restrict__ Out, int M, int N, int K,
         const float* __restrict__ tvec, const float* __restrict__ invf)
{
    extern __shared__ __align__(16) uint8_t smem[];
    const uint32_t sbase = (uint32_t)__cvta_generic_to_shared(smem);
    const int tid = threadIdx.x;
    const int wid = tid >> 5, lane = tid & 31;
    const int wm = wid & 1, wn = wid >> 1;
    const int m0 = blockIdx.y * 128, n0 = blockIdx.x * 128;
    const int lr = lane >> 2, lc = lane & 3;

    float acc[4][4][4];
#pragma unroll
    for (int a = 0; a < 4; a++)
#pragma unroll
        for (int b = 0; b < 4; b++)
#pragma unroll
            for (int c = 0; c < 4; c++) acc[a][b][c] = 0.f;

    const int NCH = K / 64;  // 12

    // issue loads for a chunk into a stage
    auto issue = [&](int ch, int st) {
        const int k0 = ch * 64;
        const uint32_t sa = sbase + (uint32_t)st * STG_SZ;
        const uint32_t sb = sa + 16384u;
#pragma unroll
        for (int it = 0; it < 4; it++) {
            int i = tid + it * 256;
            int r = i >> 3, t = i & 7;
            uint32_t soff = (uint32_t)(r * 128 + ((t ^ (r & 7)) << 4));
            cp16(sa + soff, Ah + (size_t)(m0 + r) * K + k0 + t * 8);
            cp16(sb + soff, Bh + (size_t)(n0 + r) * K + k0 + t * 8);
        }
        asm volatile("cp.async.commit_group;");
    };

    issue(0, 0);
    for (int ch = 0; ch < NCH; ch++) {
        if (ch + 1 < NCH) {
            issue(ch + 1, (ch + 1) & 1);
            asm volatile("cp.async.wait_group 1;");
        } else {
            asm volatile("cp.async.wait_group 0;");
        }
        __syncthreads();

        uint8_t* sA = smem + (size_t)(ch & 1) * STG_SZ;
        uint8_t* sB = sA + 16384;
#pragma unroll
        for (int s = 0; s < 4; s++) {
            uint32_t bf[4][2];
#pragma unroll
            for (int nt = 0; nt < 4; nt++) {
                int n = wn * 32 + nt * 8 + lr;
                uint32_t base = (uint32_t)(n * 128) + 4u * lc;
                bf[nt][0] = *(uint32_t*)(sB + base + (((2 * s) ^ (n & 7)) << 4));
                bf[nt][1] = *(uint32_t*)(sB + base + (((2 * s + 1) ^ (n & 7)) << 4));
            }
#pragma unroll
            for (int mt = 0; mt < 4; mt++) {
                int m1 = wm * 64 + mt * 16 + lr;
                int m2 = m1 + 8;
                uint32_t b1 = (uint32_t)(m1 * 128) + 4u * lc;
                uint32_t b2 = (uint32_t)(m2 * 128) + 4u * lc;
                uint32_t af[4];
                af[0] = *(uint32_t*)(sA + b1 + (((2 * s) ^ (m1 & 7)) << 4));
                af[1] = *(uint32_t*)(sA + b2 + (((2 * s) ^ (m2 & 7)) << 4));
                af[2] = *(uint32_t*)(sA + b1 + (((2 * s + 1) ^ (m1 & 7)) << 4));
                af[3] = *(uint32_t*)(sA + b2 + (((2 * s + 1) ^ (m2 & 7)) << 4));
#pragma unroll
                for (int nt = 0; nt < 4; nt++) mma_h(acc[mt][nt], af, bf[nt]);
            }
        }
        __syncthreads();
    }

    // ---- epilogue: fragment cols (2lc, 2lc+1) are RoPE pairs ----
#pragma unroll
    for (int mt = 0; mt < 4; mt++) {
        int mA = m0 + wm * 64 + mt * 16 + lr;
#pragma unroll
        for (int half = 0; half < 2; half++) {
            int m = mA + half * 8;
            float pos = 0.f;
            int bb = 0, tt = 0;
            if (MODE == 0) { bb = m / TX; tt = m % TX; pos = tvec[m]; }
            if (MODE == 1) { bb = m / TY; tt = m % TY; pos = tvec[m]; }
#pragma unroll
            for (int nt = 0; nt < 4; nt++) {
                float c0 = acc[mt][nt][half * 2 + 0];
                float c1 = acc[mt][nt][half * 2 + 1];
                int col = n0 + wn * 32 + nt * 8 + 2 * lc;
                if (MODE == 2) {
                    *(float2*)&Out[(size_t)m * N + col] = make_float2(c0, c1);
                } else if (MODE == 0) {
                    int h = col / DD, dd = col % DD;
                    float f = pos * invf[dd >> 1];
                    float sn, cs;
                    sincosf(f, &sn, &cs);
                    size_t idx = ((size_t)(bb * HH + h) * TX + tt) * DD + dd;
                    *(uint32_t*)&q_h[idx] = pack_h2(c0 * cs - c1 * sn, c1 * cs + c0 * sn);
                } else {
                    if (col < CC) {
                        int h = col / DD, dd = col % DD;
                        float f = pos * invf[dd >> 1];
                        float sn, cs;
                        sincosf(f, &sn, &cs);
                        size_t idx = ((size_t)(bb * HH + h) * TY + tt) * DD + dd;
                        *(uint32_t*)&k_h[idx] = pack_h2(c0 * cs - c1 * sn, c1 * cs + c0 * sn);
                    } else {
                        int nv = col - CC;
                        int h = nv / DD, dd = nv % DD;
                        size_t i0 = ((size_t)(bb * HH + h) * DD + dd) * TY + tt;
                        vt_h[i0]      = __float2half(c0);
                        vt_h[i0 + TY] = __float2half(c1);
                    }
                }
            }
        }
    }
}

// ---------------------------------------------------------------------------
// fp16 HMMA flash attention. Grid (TX/64, H, B), 128 threads (4 warps x 16 rows).
// ---------------------------------------------------------------------------
#define FL_SK  0u
#define FL_SV  8192u
#define FL_KT  16384u
#define FL_RNG 16640u
#define FL_SMEM 16672u

__global__ void __launch_bounds__(128)
flash_mma(const float* __restrict__ xt, const float* __restrict__ yt,
          const int* __restrict__ p_dist, const int* __restrict__ p_mind)
{
    extern __shared__ __align__(16) uint8_t sm[];
    float* kt_s = (float*)(sm + FL_KT);
    int* rng = (int*)(sm + FL_RNG);

    const int tid = threadIdx.x;
    const int wid = tid >> 5, lane = tid & 31;
    const int lr = lane >> 2, lc = lane & 3;
    const int q0 = blockIdx.x * 64;
    const int h = blockIdx.y, b = blockIdx.z;
    const float distf = (float)p_dist[0];
    const float mindf = (float)p_mind[0];
    const size_t bh = (size_t)(b * HH + h);

    const __half* Qp = q_h + bh * TX * DD;
    const __half* Kp = k_h + bh * TY * DD;
    const __half* Vp = vt_h + bh * DD * TY;
    const float* Y = yt + (size_t)b * TY;

    const int r0 = q0 + wid * 16 + lr;
    const int r1 = r0 + 8;

    uint32_t qf[4][4];
#pragma unroll
    for (int ks2 = 0; ks2 < 4; ks2++) {
        qf[ks2][0] = *(const uint32_t*)&Qp[(size_t)r0 * DD + 16 * ks2 + 2 * lc];
        qf[ks2][1] = *(const uint32_t*)&Qp[(size_t)r1 * DD + 16 * ks2 + 2 * lc];
        qf[ks2][2] = *(const uint32_t*)&Qp[(size_t)r0 * DD + 16 * ks2 + 8 + 2 * lc];
        qf[ks2][3] = *(const uint32_t*)&Qp[(size_t)r1 * DD + 16 * ks2 + 8 + 2 * lc];
    }
    const float xr0 = xt[(size_t)b * TX + r0] - mindf;
    const float xr1 = xt[(size_t)b * TX + r1] - mindf;

    if (tid == 0) {
        float xmin = xt[(size_t)b * TX + q0] - mindf;
        float xmax = xt[(size_t)b * TX + q0 + 63] - mindf;
        int lo = 0, hi = TY;
        while (lo < hi) { int mid = (lo + hi) >> 1; if (Y[mid] >= xmin - distf) hi = mid; else lo = mid + 1; }
        rng[0] = lo & ~63;
        lo = 0; hi = TY;
        while (lo < hi) { int mid = (lo + hi) >> 1; if (Y[mid] > xmax) hi = mid; else lo = mid + 1; }
        rng[1] = lo;
    }
    __syncthreads();
    const int ksr = rng[0], ker = rng[1];

    float m0r = -1e30f, m1r = -1e30f, l0r = 0.f, l1r = 0.f;
    float o[8][4];
#pragma unroll
    for (int i = 0; i < 8; i++)
#pragma unroll
        for (int j = 0; j < 4; j++) o[i][j] = 0.f;

    for (int kb = ksr; kb < ker; kb += 64) {
#pragma unroll
        for (int it = 0; it < 4; it++) {
            int i = tid + it * 128;
            int r = i >> 3, t = i & 7;
            uint32_t so = (uint32_t)(r * 128 + ((t ^ (r & 7)) << 4));
            *(uint4*)(sm + FL_SK + so) = *(const uint4*)(Kp + (size_t)(kb + r) * DD + t * 8);
            *(uint4*)(sm + FL_SV + so) = *(const uint4*)(Vp + (size_t)r * TY + kb + t * 8);
        }
        if (tid < 64) kt_s[tid] = Y[kb + tid];
        __syncthreads();

        // ---- S = Q K^T ----
        float s[8][4];
#pragma unroll
        for (int i = 0; i < 8; i++)
#pragma unroll
            for (int j = 0; j < 4; j++) s[i][j] = 0.f;
#pragma unroll
        for (int ks2 = 0; ks2 < 4; ks2++) {
#pragma unroll
            for (int nt = 0; nt < 8; nt++) {
                int n = nt * 8 + lr;
                uint32_t base = (uint32_t)(n * 128) + 4u * lc;
                uint32_t bf[2] = {*(uint32_t*)(sm + FL_SK + base + (((2 * ks2) ^ (n & 7)) << 4)),
                                  *(uint32_t*)(sm + FL_SK + base + (((2 * ks2 + 1) ^ (n & 7)) << 4))};
                mma_h(s[nt], qf[ks2], bf);
            }
        }

        // ---- mask + scale ----
#pragma unroll
        for (int nt = 0; nt < 8; nt++) {
#pragma unroll
            for (int j = 0; j < 2; j++) {
                float yv = kt_s[nt * 8 + 2 * lc + j];
                bool ok0 = (xr0 >= yv) && (xr0 <= yv + distf);
                bool ok1 = (xr1 >= yv) && (xr1 <= yv + distf);
                s[nt][j]     = ok0 ? s[nt][j] * 0.125f     : -1e30f;
                s[nt][j + 2] = ok1 ? s[nt][j + 2] * 0.125f : -1e30f;
            }
        }
        // ---- online softmax ----
        float mx0 = -1e30f, mx1 = -1e30f;
#pragma unroll
        for (int nt = 0; nt < 8; nt++) {
            mx0 = fmaxf(mx0, fmaxf(s[nt][0], s[nt][1]));
            mx1 = fmaxf(mx1, fmaxf(s[nt][2], s[nt][3]));
        }
        mx0 = fmaxf(mx0, __shfl_xor_sync(0xffffffffu, mx0, 1));
        mx0 = fmaxf(mx0, __shfl_xor_sync(0xffffffffu, mx0, 2));
        mx1 = fmaxf(mx1, __shfl_xor_sync(0xffffffffu, mx1, 1));
        mx1 = fmaxf(mx1, __shfl_xor_sync(0xffffffffu, mx1, 2));
        float mn0 = fmaxf(m0r, mx0), mn1 = fmaxf(m1r, mx1);
        float f0 = __expf(m0r - mn0), f1 = __expf(m1r - mn1);

        uint32_t pp[8][2];
        float sum0 = 0.f, sum1 = 0.f;
#pragma unroll
        for (int nt = 0; nt < 8; nt++) {
            float p00 = (s[nt][0] <= -1e29f) ? 0.f : __expf(s[nt][0] - mn0);
            float p01 = (s[nt][1] <= -1e29f) ? 0.f : __expf(s[nt][1] - mn0);
            float p10 = (s[nt][2] <= -1e29f) ? 0.f : __expf(s[nt][2] - mn1);
            float p11 = (s[nt][3] <= -1e29f) ? 0.f : __expf(s[nt][3] - mn1);
            sum0 += p00 + p01;
            sum1 += p10 + p11;
            pp[nt][0] = pack_h2(p00, p01);
            pp[nt][1] = pack_h2(p10, p11);
        }
        sum0 += __shfl_xor_sync(0xffffffffu, sum0, 1);
        sum0 += __shfl_xor_sync(0xffffffffu, sum0, 2);
        sum1 += __shfl_xor_sync(0xffffffffu, sum1, 1);
        sum1 += __shfl_xor_sync(0xffffffffu, sum1, 2);
        l0r = l0r * f0 + sum0;
        l1r = l1r * f1 + sum1;
        m0r = mn0;
        m1r = mn1;
#pragma unroll
        for (int nd = 0; nd < 8; nd++) {
            o[nd][0] *= f0; o[nd][1] *= f0;
            o[nd][2] *= f1; o[nd][3] *= f1;
        }

        // ---- O += P V ----
#pragma unroll
        for (int kp = 0; kp < 4; kp++) {
            uint32_t af[4] = {pp[2 * kp][0], pp[2 * kp][1], pp[2 * kp + 1][0], pp[2 * kp + 1][1]};
#pragma unroll
            for (int nd = 0; nd < 8; nd++) {
                int n = nd * 8 + lr;
                uint32_t base = (uint32_t)(n * 128) + 4u * lc;
                uint32_t bf[2] = {*(uint32_t*)(sm + FL_SV + base + (((2 * kp) ^ (n & 7)) << 4)),
                                  *(uint32_t*)(sm + FL_SV + base + (((2 * kp + 1) ^ (n & 7)) << 4))};
                mma_h(o[nd], af, bf);
            }
        }
        __syncthreads();
    }

    // ---- epilogue: O/l -> go_h fp16 ----
    float rc0 = (l0r > 0.f) ? 1.f / l0r : 0.f;
    float rc1 = (l1r > 0.f) ? 1.f / l1r : 0.f;
#pragma unroll
    for (int nd = 0; nd < 8; nd++) {
        int d0 = nd * 8 + 2 * lc;
        size_t i0 = ((size_t)b * TX + r0) * CC + h * DD + d0;
        *(uint32_t*)&go_h[i0] = pack_h2(o[nd][0] * rc0, o[nd][1] * rc0);
        size_t i1 = ((size_t)b * TX + r1) * CC + h * DD + d0;
        *(uint32_t*)&go_h[i1] = pack_h2(o[nd][2] * rc1, o[nd][3] * rc1);
    }
}

extern "C" void kernel_launch(void* const* d_in, const int* in_sizes, int n_in,
                              void* d_out, int out_size) {
    const float* x    = (const float*)d_in[0];
    const float* x_t  = (const float*)d_in[1];
    const float* y    = (const float*)d_in[2];
    const float* y_t  = (const float*)d_in[3];
    const int*   dist = (const int*)d_in[4];
    const int*   mind = (const int*)d_in[5];
    const float* Wq   = (const float*)d_in[6];
    const float* Wkv  = (const float*)d_in[7];
    const float* Wpr  = (const float*)d_in[8];
    const float* invf = (const float*)d_in[9];
    float* out = (float*)d_out;

    __half *p_gx, *p_gy, *p_go, *p_wq, *p_wkv, *p_wp;
    cudaGetSymbolAddress((void**)&p_gx, gx_h);
    cudaGetSymbolAddress((void**)&p_gy, gy_h);
    cudaGetSymbolAddress((void**)&p_go, go_h);
    cudaGetSymbolAddress((void**)&p_wq, gwq_h);
    cudaGetSymbolAddress((void**)&p_wkv, gwkv_h);
    cudaGetSymbolAddress((void**)&p_wp, gwp_h);

    cudaFuncSetAttribute(gemm_mma<0>, cudaFuncAttributeMaxDynamicSharedMemorySize, GEMM_SMEM);
    cudaFuncSetAttribute(gemm_mma<1>, cudaFuncAttributeMaxDynamicSharedMemorySize, GEMM_SMEM);
    cudaFuncSetAttribute(gemm_mma<2>, cudaFuncAttributeMaxDynamicSharedMemorySize, GEMM_SMEM);
    cudaFuncSetAttribute(flash_mma, cudaFuncAttributeMaxDynamicSharedMemorySize, FL_SMEM);

    // prep: fp16 conversions + weight transposes
    fcvt<<<(Bz * TX * CC / 4 + 255) / 256, 256>>>(x, p_gx, Bz * TX * CC / 4);
    fcvt<<<(Bz * TY * CC / 4 + 255) / 256, 256>>>(y, p_gy, Bz * TY * CC / 4);
    wtrans<<<dim3(CC / 32, CC / 32), 256>>>(Wq, p_wq, CC, CC);
    wtrans<<<dim3(2 * CC / 32, CC / 32), 256>>>(Wkv, p_wkv, CC, 2 * CC);
    wtrans<<<dim3(CC / 32, CC / 32), 256>>>(Wpr, p_wp, CC, CC);

    // q = rope(x @ Wq) -> q_h
    gemm_mma<0><<<dim3(CC / 128, (Bz * TX) / 128), 256, GEMM_SMEM>>>(
        p_gx, p_wq, nullptr, Bz * TX, CC, CC, x_t, invf);
    // kv = y @ Wkv -> k_h (RoPE), vt_h (transposed)
    gemm_mma<1><<<dim3(2 * CC / 128, (Bz * TY) / 128), 256, GEMM_SMEM>>>(
        p_gy, p_wkv, nullptr, Bz * TY, 2 * CC, CC, y_t, invf);
    // windowed flash attention (fp16 HMMA) -> go_h
    flash_mma<<<dim3(TX / 64, HH, Bz), 128, FL_SMEM>>>(x_t, y_t, dist, mind);
    // out = o @ Wproj
    gemm_mma<2><<<dim3(CC / 128, (Bz * TX) / 128), 256, GEMM_SMEM>>>(
        p_go, p_wp, out, Bz * TX, CC, CC, nullptr, nullptr);
}